// round 6
// baseline (speedup 1.0000x reference)
#include <cuda_runtime.h>
#include <cuda_fp16.h>
#include <cstdint>

// out = x @ kernel[2]  (seq_len==1 -> softmax over length-1 axis is identity)
// x: [8192,1024] f32, kernel: [3,1024,1024] f32, out: [8192,1024] f32
#define BROWS 8192
#define DDIM  1024

__device__ __half g_wh[DDIM * DDIM];    // 2 MB, [K,N] row-major

// ------------------------- PTX helpers -------------------------
static __device__ __forceinline__ uint32_t smem_u32(const void* p) {
    uint32_t a;
    asm("{ .reg .u64 t; cvta.to.shared.u64 t, %1; cvt.u32.u64 %0, t; }" : "=r"(a) : "l"(p));
    return a;
}
static __device__ __forceinline__ void cpa16(uint32_t saddr, const void* gptr) {
    asm volatile("cp.async.cg.shared.global [%0], [%1], 16;" :: "r"(saddr), "l"(gptr));
}
static __device__ __forceinline__ void cp_commit() {
    asm volatile("cp.async.commit_group;" ::: "memory");
}
static __device__ __forceinline__ void cp_wait2() {
    asm volatile("cp.async.wait_group 2;" ::: "memory");
}
static __device__ __forceinline__ void cp_wait1() {
    asm volatile("cp.async.wait_group 1;" ::: "memory");
}
static __device__ __forceinline__ void cp_wait0() {
    asm volatile("cp.async.wait_group 0;" ::: "memory");
}
static __device__ __forceinline__ void ldsm4(uint32_t* r, uint32_t a) {
    asm volatile("ldmatrix.sync.aligned.m8n8.x4.shared.b16 {%0,%1,%2,%3}, [%4];"
                 : "=r"(r[0]), "=r"(r[1]), "=r"(r[2]), "=r"(r[3]) : "r"(a));
}
static __device__ __forceinline__ void ldsm4t(uint32_t* r, uint32_t a) {
    asm volatile("ldmatrix.sync.aligned.m8n8.x4.trans.shared.b16 {%0,%1,%2,%3}, [%4];"
                 : "=r"(r[0]), "=r"(r[1]), "=r"(r[2]), "=r"(r[3]) : "r"(a));
}
static __device__ __forceinline__ void mma16816(float* c, const uint32_t* a, const uint32_t* b) {
    asm volatile(
        "mma.sync.aligned.m16n8k16.row.col.f32.f16.f16.f32 "
        "{%0,%1,%2,%3}, {%4,%5,%6,%7}, {%8,%9}, {%0,%1,%2,%3};"
        : "+f"(c[0]), "+f"(c[1]), "+f"(c[2]), "+f"(c[3])
        : "r"(a[0]), "r"(a[1]), "r"(a[2]), "r"(a[3]), "r"(b[0]), "r"(b[1]));
}
static __device__ __forceinline__ void sts64(uint32_t addr, uint32_t v0, uint32_t v1) {
    asm volatile("st.shared.v2.b32 [%0], {%1, %2};" :: "r"(addr), "r"(v0), "r"(v1) : "memory");
}

// ------------------------- w convert kernel -------------------------
__global__ void __launch_bounds__(256) wcvt_kernel(const float4* __restrict__ w) {
    int i = blockIdx.x * 512 + threadIdx.x;
    uint2* dst = (uint2*)g_wh;
#pragma unroll
    for (int j = 0; j < 2; j++) {
        float4 v = w[i + j * 256];
        __half2 lo = __floats2half2_rn(v.x, v.y);
        __half2 hi = __floats2half2_rn(v.z, v.w);
        dst[i + j * 256] = make_uint2(*(uint32_t*)&lo, *(uint32_t*)&hi);
    }
}

// ------------------------- fused convert + GEMM -------------------------
// BM=128, BN=256, BK=64, 4 stages. 512 threads = 16 warps (4x4), warp tile 32x64.
// Stage: A16 16KB [128 rows x 128B swizzled] | B 32KB [64 k-rows x 512B swizzled].
// A is loaded f32 from gmem via LDG, converted in regs, STS'd 2 k-tiles ahead.
#define ST_B_OFF    16384
#define STAGE_BYTES 49152
#define N_STAGES    4
#define GEMM_SMEM   (N_STAGES * STAGE_BYTES)   // 196608

__global__ void __launch_bounds__(512, 1) gemm_fused_kernel(const float* __restrict__ x,
                                                            float* __restrict__ out) {
    extern __shared__ char smem[];
    const uint32_t sb = smem_u32(smem);
    const int tid    = threadIdx.x;
    const int lane   = tid & 31;
    const int wid    = tid >> 5;
    const int warp_m = wid >> 2;   // 0..3 -> m offset *32
    const int warp_n = wid & 3;    // 0..3 -> n offset *64
    const int cta_m  = blockIdx.y * 128;
    const int cta_n  = blockIdx.x * 256;

    // Per-thread A-convert geometry: 4 float4 chunks (32KB f32 per k-tile).
    // ch = tid + i*512; row r = ch>>4 (16 float4 per 64-float row), c = ch&15.
    const float4* xa = (const float4*)x;

    // f32 LDG for k-tile kt into 4 float4 regs
    auto ldg_a = [&](int kt, float4* R) {
#pragma unroll
        for (int i = 0; i < 4; i++) {
            int ch = tid + i * 512;
            int r = ch >> 4, c = ch & 15;
            R[i] = xa[(size_t)(cta_m + r) * 256 + kt * 16 + c];
        }
    };
    // convert + STS into swizzled fp16 A stage s
    auto cvt_a = [&](int s, const float4* R) {
        uint32_t st = sb + s * STAGE_BYTES;
#pragma unroll
        for (int i = 0; i < 4; i++) {
            int ch = tid + i * 512;
            int r = ch >> 4, c = ch & 15;
            __half2 lo = __floats2half2_rn(R[i].x, R[i].y);
            __half2 hi = __floats2half2_rn(R[i].z, R[i].w);
            uint32_t addr = st + r * 128 + (((c >> 1) ^ (r & 7)) * 16) + (c & 1) * 8;
            sts64(addr, *(uint32_t*)&lo, *(uint32_t*)&hi);
        }
    };
    // B fp16 cp.async for k-tile kt into stage s
    auto load_b = [&](int kt, int s) {
        uint32_t st = sb + s * STAGE_BYTES + ST_B_OFF;
#pragma unroll
        for (int i = 0; i < 4; i++) {
            int ch = tid + i * 512;
            int k = ch >> 5, c = ch & 31;
            size_t g = (size_t)(kt * 64 + k) * DDIM + cta_n + c * 8;
            cpa16(st + k * 512 + ((c ^ (k & 7)) * 16), g_wh + g);
        }
    };

    float c[2][8][4];
#pragma unroll
    for (int i = 0; i < 2; i++)
#pragma unroll
        for (int j = 0; j < 8; j++)
#pragma unroll
            for (int q = 0; q < 4; q++) c[i][j][q] = 0.0f;

    // Prologue: B stages 0..2 in flight; A16 stages 0,1 converted.
    load_b(0, 0); cp_commit();
    load_b(1, 1); cp_commit();
    load_b(2, 2); cp_commit();
    {
        float4 R0[4], R1[4];
        ldg_a(0, R0);
        ldg_a(1, R1);
        cvt_a(0, R0);
        cvt_a(1, R1);
    }

    for (int kt = 0; kt < 16; kt++) {
        if (kt < 14)       cp_wait2();
        else if (kt == 14) cp_wait1();
        else               cp_wait0();
        __syncthreads();

        // Prefetch: f32 A for kt+2 (LDG latency hidden under first half of MMA),
        // B for kt+3 via cp.async.
        float4 R[4];
        const bool do_a = (kt + 2 < 16);
        if (do_a) ldg_a(kt + 2, R);
        if (kt + 3 < 16) {
            load_b(kt + 3, (kt + 3) & 3);
            cp_commit();
        }

        uint32_t st = sb + (kt & 3) * STAGE_BYTES;
#pragma unroll
        for (int kk = 0; kk < 4; kk++) {
            uint32_t a[2][4], b[4][4];
#pragma unroll
            for (int mt = 0; mt < 2; mt++) {
                int row = warp_m * 32 + mt * 16 + (lane & 15);
                int ch  = kk * 2 + (lane >> 4);
                ldsm4(a[mt], st + row * 128 + ((ch ^ (row & 7)) * 16));
            }
#pragma unroll
            for (int nt = 0; nt < 4; nt++) {
                int k  = kk * 16 + (lane & 15);
                int nc = warp_n * 8 + nt * 2 + (lane >> 4);
                ldsm4t(b[nt], st + ST_B_OFF + k * 512 + ((nc ^ (k & 7)) * 16));
            }
#pragma unroll
            for (int mt = 0; mt < 2; mt++)
#pragma unroll
                for (int nj = 0; nj < 8; nj++)
                    mma16816(c[mt][nj], a[mt], &b[nj >> 1][(nj & 1) * 2]);

            // After the second kk-step, the f32 LDGs have landed: convert + STS
            // into stage (kt+2)&3 (slot freed 2 barriers ago).
            if (kk == 1 && do_a) cvt_a((kt + 2) & 3, R);
        }
    }

    // Epilogue: direct f32 stores from fragments
#pragma unroll
    for (int mt = 0; mt < 2; mt++) {
#pragma unroll
        for (int nj = 0; nj < 8; nj++) {
            int row = cta_m + warp_m * 32 + mt * 16 + (lane >> 2);
            int col = cta_n + warp_n * 64 + nj * 8 + (lane & 3) * 2;
            *reinterpret_cast<float2*>(&out[(size_t)row * DDIM + col]) =
                make_float2(c[mt][nj][0], c[mt][nj][1]);
            *reinterpret_cast<float2*>(&out[(size_t)(row + 8) * DDIM + col]) =
                make_float2(c[mt][nj][2], c[mt][nj][3]);
        }
    }
}

// ------------------------- launch -------------------------
extern "C" void kernel_launch(void* const* d_in, const int* in_sizes, int n_in,
                              void* d_out, int out_size) {
    const float* x = (const float*)d_in[0];                 // [8192,1024]
    const float* kern = (const float*)d_in[1];              // [3,1024,1024]
    const float* wv = kern + 2L * DDIM * DDIM;              // kernel[2]: [K,N]
    float* out = (float*)d_out;

    const int nw4 = DDIM * DDIM / 4;    // 262,144 float4
    wcvt_kernel<<<nw4 / 512, 256>>>((const float4*)wv);

    cudaFuncSetAttribute(gemm_fused_kernel,
                         cudaFuncAttributeMaxDynamicSharedMemorySize, GEMM_SMEM);
    dim3 grid(DDIM / 256, BROWS / 128);  // (4, 64) = 256 CTAs
    gemm_fused_kernel<<<grid, 512, GEMM_SMEM>>>(x, out);
}

// round 7
// speedup vs baseline: 1.0627x; 1.0627x over previous
#include <cuda_runtime.h>
#include <cuda_fp16.h>
#include <cstdint>

// out = x @ kernel[2]  (seq_len==1 -> softmax over length-1 axis is identity)
// x: [8192,1024] f32, kernel: [3,1024,1024] f32, out: [8192,1024] f32
#define BROWS 8192
#define DDIM  1024

__device__ __half g_xh[BROWS * DDIM];   // 16 MB
__device__ __half g_wh[DDIM * DDIM];    // 2 MB, [K,N] row-major

// ------------------------- PTX helpers -------------------------
static __device__ __forceinline__ uint32_t smem_u32(const void* p) {
    uint32_t a;
    asm("{ .reg .u64 t; cvta.to.shared.u64 t, %1; cvt.u32.u64 %0, t; }" : "=r"(a) : "l"(p));
    return a;
}
static __device__ __forceinline__ void cpa16(uint32_t saddr, const void* gptr) {
    asm volatile("cp.async.cg.shared.global [%0], [%1], 16;" :: "r"(saddr), "l"(gptr));
}
static __device__ __forceinline__ void cp_commit() {
    asm volatile("cp.async.commit_group;" ::: "memory");
}
static __device__ __forceinline__ void cp_wait2() {
    asm volatile("cp.async.wait_group 2;" ::: "memory");
}
static __device__ __forceinline__ void cp_wait1() {
    asm volatile("cp.async.wait_group 1;" ::: "memory");
}
static __device__ __forceinline__ void cp_wait0() {
    asm volatile("cp.async.wait_group 0;" ::: "memory");
}
static __device__ __forceinline__ void ldsm4(uint32_t* r, uint32_t a) {
    asm volatile("ldmatrix.sync.aligned.m8n8.x4.shared.b16 {%0,%1,%2,%3}, [%4];"
                 : "=r"(r[0]), "=r"(r[1]), "=r"(r[2]), "=r"(r[3]) : "r"(a));
}
static __device__ __forceinline__ void ldsm4t(uint32_t* r, uint32_t a) {
    asm volatile("ldmatrix.sync.aligned.m8n8.x4.trans.shared.b16 {%0,%1,%2,%3}, [%4];"
                 : "=r"(r[0]), "=r"(r[1]), "=r"(r[2]), "=r"(r[3]) : "r"(a));
}
static __device__ __forceinline__ void mma16816(float* c, const uint32_t* a, const uint32_t* b) {
    asm volatile(
        "mma.sync.aligned.m16n8k16.row.col.f32.f16.f16.f32 "
        "{%0,%1,%2,%3}, {%4,%5,%6,%7}, {%8,%9}, {%0,%1,%2,%3};"
        : "+f"(c[0]), "+f"(c[1]), "+f"(c[2]), "+f"(c[3])
        : "r"(a[0]), "r"(a[1]), "r"(a[2]), "r"(a[3]), "r"(b[0]), "r"(b[1]));
}

// ------------------------- convert kernel -------------------------
// Blocks 0..2047 convert x, 2048..2303 convert w (nx4 = 2048*1024, exact split).
__global__ void __launch_bounds__(256) cvt_kernel(const float4* __restrict__ x,
                                                  const float4* __restrict__ w,
                                                  int nx4) {
    int base = blockIdx.x * 1024 + threadIdx.x;
    const float4* src;
    uint2* dst;
    if (base < nx4) {
        src = x;
        dst = (uint2*)g_xh;
    } else {
        src = w - nx4;
        dst = ((uint2*)g_wh) - nx4;
    }
    float4 v[4];
#pragma unroll
    for (int j = 0; j < 4; j++) v[j] = src[base + j * 256];
#pragma unroll
    for (int j = 0; j < 4; j++) {
        __half2 lo = __floats2half2_rn(v[j].x, v[j].y);
        __half2 hi = __floats2half2_rn(v[j].z, v[j].w);
        dst[base + j * 256] = make_uint2(*(uint32_t*)&lo, *(uint32_t*)&hi);
    }
}

// ------------------------- GEMM -------------------------
// BM=128, BN=64, BK=64, 4 stages, 2 CTAs/SM. 256 threads = 8 warps (4x2),
// warp tile 32x32. Stage: A 16KB [128 rows x 128B sw] | B 8KB [64 k-rows x 128B sw].
#define ST_B_OFF    16384
#define STAGE_BYTES 24576
#define N_STAGES    4
#define GEMM_SMEM   (N_STAGES * STAGE_BYTES)   // 98304

__global__ void __launch_bounds__(256, 2) gemm_fp16_kernel(float* __restrict__ out) {
    extern __shared__ char smem[];
    const uint32_t sb = smem_u32(smem);
    const int tid    = threadIdx.x;
    const int lane   = tid & 31;
    const int wid    = tid >> 5;
    const int warp_m = wid >> 1;   // 0..3 -> m offset *32
    const int warp_n = wid & 1;    // 0..1 -> n offset *32
    const int cta_m  = blockIdx.y * 128;
    const int cta_n  = blockIdx.x * 64;

    auto load_st = [&](int kt, int s) {
        uint32_t st = sb + s * STAGE_BYTES;
        // A: 128 rows x 8 chunks of 16B = 1024 chunks, 4/thread
#pragma unroll
        for (int i = 0; i < 4; i++) {
            int ch = tid + i * 256;
            int r = ch >> 3, c = ch & 7;
            size_t g = (size_t)(cta_m + r) * DDIM + kt * 64 + c * 8;
            cpa16(st + r * 128 + ((c ^ (r & 7)) * 16), g_xh + g);
        }
        // B: 64 k-rows x 8 chunks of 16B = 512 chunks, 2/thread
#pragma unroll
        for (int i = 0; i < 2; i++) {
            int ch = tid + i * 256;
            int k = ch >> 3, c = ch & 7;
            size_t g = (size_t)(kt * 64 + k) * DDIM + cta_n + c * 8;
            cpa16(st + ST_B_OFF + k * 128 + ((c ^ (k & 7)) * 16), g_wh + g);
        }
    };

    float c[2][4][4];
#pragma unroll
    for (int i = 0; i < 2; i++)
#pragma unroll
        for (int j = 0; j < 4; j++)
#pragma unroll
            for (int q = 0; q < 4; q++) c[i][j][q] = 0.0f;

    load_st(0, 0); cp_commit();
    load_st(1, 1); cp_commit();
    load_st(2, 2); cp_commit();

    for (int kt = 0; kt < 16; kt++) {
        if (kt < 14)       cp_wait2();
        else if (kt == 14) cp_wait1();
        else               cp_wait0();
        __syncthreads();
        if (kt + 3 < 16) {
            load_st(kt + 3, (kt + 3) & 3);
            cp_commit();
        }

        uint32_t st = sb + (kt & 3) * STAGE_BYTES;
#pragma unroll
        for (int kk = 0; kk < 4; kk++) {
            uint32_t a[2][4], b[2][4];
#pragma unroll
            for (int mt = 0; mt < 2; mt++) {
                int row = warp_m * 32 + mt * 16 + (lane & 15);
                int ch  = kk * 2 + (lane >> 4);
                ldsm4(a[mt], st + row * 128 + ((ch ^ (row & 7)) * 16));
            }
#pragma unroll
            for (int nt = 0; nt < 2; nt++) {
                int k  = kk * 16 + (lane & 15);
                int nc = warp_n * 4 + nt * 2 + (lane >> 4);
                ldsm4t(b[nt], st + ST_B_OFF + k * 128 + ((nc ^ (k & 7)) * 16));
            }
#pragma unroll
            for (int mt = 0; mt < 2; mt++)
#pragma unroll
                for (int nj = 0; nj < 4; nj++)
                    mma16816(c[mt][nj], a[mt], &b[nj >> 1][(nj & 1) * 2]);
        }
    }

    // Epilogue: direct f32 stores from fragments
#pragma unroll
    for (int mt = 0; mt < 2; mt++) {
#pragma unroll
        for (int nj = 0; nj < 4; nj++) {
            int row = cta_m + warp_m * 32 + mt * 16 + (lane >> 2);
            int col = cta_n + warp_n * 32 + nj * 8 + (lane & 3) * 2;
            *reinterpret_cast<float2*>(&out[(size_t)row * DDIM + col]) =
                make_float2(c[mt][nj][0], c[mt][nj][1]);
            *reinterpret_cast<float2*>(&out[(size_t)(row + 8) * DDIM + col]) =
                make_float2(c[mt][nj][2], c[mt][nj][3]);
        }
    }
}

// ------------------------- launch -------------------------
extern "C" void kernel_launch(void* const* d_in, const int* in_sizes, int n_in,
                              void* d_out, int out_size) {
    const float* x = (const float*)d_in[0];                 // [8192,1024]
    const float* kern = (const float*)d_in[1];              // [3,1024,1024]
    const float* wv = kern + 2L * DDIM * DDIM;              // kernel[2]: [K,N]
    float* out = (float*)d_out;

    const int nx4 = BROWS * DDIM / 4;   // 2,097,152 (= 2048 blocks * 1024)
    const int nw4 = DDIM * DDIM / 4;    // 262,144   (= 256 blocks * 1024)
    cvt_kernel<<<(nx4 + nw4) / 1024, 256>>>((const float4*)x, (const float4*)wv, nx4);

    cudaFuncSetAttribute(gemm_fp16_kernel,
                         cudaFuncAttributeMaxDynamicSharedMemorySize, GEMM_SMEM);
    dim3 grid(DDIM / 64, BROWS / 128);  // (16, 64) = 1024 CTAs, x-major shares A in L2
    gemm_fp16_kernel<<<grid, 256, GEMM_SMEM>>>(out);
}